// round 15
// baseline (speedup 1.0000x reference)
#include <cuda_runtime.h>
#include <cuda_fp16.h>
#include <cstdint>
#include <math.h>

// Problem constants (B=4, S=2048 -> T=8192)
constexpr int T_TOK = 8192;
constexpr int D_DIM = 1024;
constexpr int F_DIM = 4096;
constexpr int E_NUM = 8;

// ---------------- device scratch (static globals; no allocation) ----------------
// All fp16 GEMM operand buffers use a k-interleaved layout: within each group of
// 16 halfs along k, logical index k sits at perm16(k). This makes each MMA
// fragment pair ((a0,a2) / (b0,b1)) one aligned 8-byte word -> LDS.64.
__device__ __half g_xh [(size_t)T_TOK * D_DIM];           //  16 MB  fp16 x (k-interleaved)
__device__ __half g_W1t[(size_t)E_NUM * F_DIM * D_DIM];   //  67 MB  W1^T [E][F][D] k-interleaved
__device__ __half g_W2t[(size_t)E_NUM * D_DIM * F_DIM];   //  67 MB  W2^T [E][D][F] k-interleaved
__device__ __half g_H  [(size_t)E_NUM * T_TOK * F_DIM];   // 537 MB  GELU hidden fp16, k-interleaved
__device__ float  g_Y  [(size_t)T_TOK * 2 * D_DIM];       //  67 MB  (token,slot) output (natural)
__device__ float  g_gates[T_TOK * 2];
__device__ int    g_asg[E_NUM * T_TOK];                   // expert-local row -> token*2+slot
__device__ int    g_cnt[E_NUM];

// ---------------- helpers ----------------
// perm16: logical k (0..15) -> physical slot. Groups (2t,2t+1,2t+8,2t+9) contiguous.
__device__ __forceinline__ int perm16(int k) {
    return ((k >> 1) & 3) * 4 + ((k >> 3) & 1) * 2 + (k & 1);
}
__device__ __forceinline__ float gelu_exact(float v) {
    return 0.5f * v * (1.0f + erff(v * 0.7071067811865476f));
}
__device__ __forceinline__ uint32_t smem_u32(const void* p) {
    return (uint32_t)__cvta_generic_to_shared(p);
}
__device__ __forceinline__ void cp_async16(uint32_t dst, const void* src) {
    asm volatile("cp.async.cg.shared.global [%0], [%1], 16;\n"
                 :: "r"(dst), "l"(src) : "memory");
}
__device__ __forceinline__ void mma16816(float* c, const uint32_t* a, const uint32_t* b) {
    asm volatile(
        "mma.sync.aligned.m16n8k16.row.col.f32.f16.f16.f32 "
        "{%0,%1,%2,%3}, {%4,%5,%6,%7}, {%8,%9}, {%0,%1,%2,%3};\n"
        : "+f"(c[0]), "+f"(c[1]), "+f"(c[2]), "+f"(c[3])
        : "r"(a[0]), "r"(a[1]), "r"(a[2]), "r"(a[3]), "r"(b[0]), "r"(b[1]));
}

// ---------------- kernel 0: reset counters ----------------
__global__ void init_kernel() {
    if (threadIdx.x < E_NUM) g_cnt[threadIdx.x] = 0;
}

// ---------------- kernel 1: gating + fused x->fp16 convert (k-interleaved store) --------
__global__ void gating_kernel(const float* __restrict__ x,
                              const float* __restrict__ Wg,
                              const float* __restrict__ bg) {
    int t = blockIdx.x * 8 + (threadIdx.x >> 5);
    int lane = threadIdx.x & 31;
    float acc[E_NUM];
#pragma unroll
    for (int e = 0; e < E_NUM; e++) acc[e] = 0.0f;
    const float* xr = x + (size_t)t * D_DIM;
    __half* xo = g_xh + (size_t)t * D_DIM;
    for (int d = lane; d < D_DIM; d += 32) {
        float xv = xr[d];
        xo[(d & ~15) | perm16(d & 15)] = __float2half_rn(xv);
        const float* w = Wg + (size_t)d * E_NUM;
#pragma unroll
        for (int e = 0; e < E_NUM; e++) acc[e] += xv * w[e];
    }
#pragma unroll
    for (int e = 0; e < E_NUM; e++) {
#pragma unroll
        for (int o = 16; o > 0; o >>= 1)
            acc[e] += __shfl_xor_sync(0xffffffffu, acc[e], o);
    }
    if (lane == 0) {
        float l[E_NUM];
#pragma unroll
        for (int e = 0; e < E_NUM; e++) l[e] = acc[e] + bg[e];
        int i0 = 0;
#pragma unroll
        for (int e = 1; e < E_NUM; e++) if (l[e] > l[i0]) i0 = e;
        int i1 = (i0 == 0) ? 1 : 0;
#pragma unroll
        for (int e = 0; e < E_NUM; e++) if (e != i0 && l[e] > l[i1]) i1 = e;

        float dd = expf(l[i1] - l[i0]);
        float inv = 1.0f / (1.0f + dd);
        g_gates[2 * t]     = inv;
        g_gates[2 * t + 1] = dd * inv;
        int p0 = atomicAdd(&g_cnt[i0], 1);
        g_asg[i0 * T_TOK + p0] = 2 * t;
        int p1 = atomicAdd(&g_cnt[i1], 1);
        g_asg[i1 * T_TOK + p1] = 2 * t + 1;
    }
}

// ---------------- kernel 3: transpose + fp16 (k-interleaved store) ----------------
// dst symbol resolved in device code (GB300 ATS shadow-symbol pitfall).
template <int WHICH>   // 0 -> g_W1t, 1 -> g_W2t
__global__ void transpose_cvt_kernel(const float* __restrict__ in, int R, int C) {
    __shared__ float tile[32][33];
    __half* out = (WHICH == 0) ? g_W1t : g_W2t;
    int e = blockIdx.z;
    const float* src = in + (size_t)e * R * C;
    __half* dst = out + (size_t)e * R * C;
    int c0 = blockIdx.x * 32, r0 = blockIdx.y * 32;
    int tx = threadIdx.x, ty = threadIdx.y;
#pragma unroll
    for (int i = ty; i < 32; i += 8)
        tile[i][tx] = src[(size_t)(r0 + i) * C + c0 + tx];
    __syncthreads();
    int kp = (r0 + (tx & ~15)) | perm16(tx & 15);   // k index with intra-16 interleave
#pragma unroll
    for (int i = ty; i < 32; i += 8)
        dst[(size_t)(c0 + i) * R + kp] = __float2half_rn(tile[tx][i]);
}

// ---------------- kernels 4/5: grouped GEMM — R12 core + 32-bit hoisted load offsets -----
// LDS.64 fragments via k-interleaved operands; 64x64 warp tiles; 3 CTAs/SM; STAGES=3.
// Load addressing: per-thread 32-bit offsets (aoff/boff/doff) computed ONCE; the per-kt
// s_tok LDS reads and 64-bit address chains are gone. (R13's failure used persistent
// 64-bit pointers; these are narrow ints.)
// PHASE1: H[row, n] = fp16(GELU(gather(g_xh) @ W1t[e][n,:] + b1[e,n]))   K=1024, N=4096
// PHASE2: Y[asg, n] =        H[row,:] @ W2t[e][n,:] + b2[e,n]            K=4096, N=1024
template <int KDIM, int NDIM, bool PHASE1>
__global__ void __launch_bounds__(128, 3)
moe_hgemm(const float* __restrict__ bias) {
    constexpr int BM = 128, BN = 128, BK = 32, STAGES = 3;
    constexpr int ROW_B = 96;                    // padded row stride in bytes (24 words)
    constexpr int TILE_B = BM * ROW_B;           // 12288 bytes per operand tile
    constexpr int STG = 2 * TILE_B;              // 24576 bytes per stage
    constexpr int KT = KDIM / BK;

    extern __shared__ __align__(16) char dsm[];
    __shared__ int s_tok[BM];

    const int e = blockIdx.z;
    const int cnt = g_cnt[e];
    const int m0 = blockIdx.y * BM;
    if (m0 >= cnt) return;
    const int n0 = blockIdx.x * BN;
    const int tid = threadIdx.x;

    const __half* Ab = PHASE1 ? g_xh : (g_H + ((size_t)e * T_TOK + m0) * KDIM);
    const __half* Bb = (PHASE1 ? g_W1t : g_W2t) + ((size_t)e * NDIM + n0) * KDIM;

    if (PHASE1) {
        int m = m0 + tid;
        s_tok[tid] = (m < cnt) ? (g_asg[e * T_TOK + m] >> 1) : 0;  // pad rows read token 0
        __syncthreads();
    }

    const uint32_t sbase = smem_u32(dsm);

    // ---- per-thread 32-bit load offsets, computed once ----
    int aoff[4], boff[4];
    uint32_t doff[4];
#pragma unroll
    for (int i = 0; i < 4; ++i) {
        int idx = tid + i * 128;
        int r = idx >> 2, c = idx & 3;           // row 0..127, chunk 0..3 (16B = 8 halfs)
        if (PHASE1) {
            aoff[i] = s_tok[r] * KDIM + c * 8;   // vs g_xh base
        } else {
            int m = m0 + r;
            aoff[i] = (m < cnt ? r : 0) * KDIM + c * 8;   // vs Ab
        }
        boff[i] = r * KDIM + c * 8;
        doff[i] = (uint32_t)(r * ROW_B + c * 16);
    }
    const __half* Abase = PHASE1 ? g_xh : Ab;

    auto load_stage = [&](int kt, int s) {
        uint32_t st = sbase + s * STG;
        const int kb = kt * BK;
#pragma unroll
        for (int i = 0; i < 4; ++i) {
            cp_async16(st + doff[i], Abase + aoff[i] + kb);
            cp_async16(st + TILE_B + doff[i], Bb + boff[i] + kb);
        }
    };

    const int lane = tid & 31;
    const int warp = tid >> 5;
    const int wm = warp & 1;        // 2 warps over M (64 rows each)
    const int wn = warp >> 1;       // 2 warps over N (64 cols each)
    const int g = lane >> 2, tg = lane & 3;

    float acc[4][8][4];             // mi x ni x frag  (64x64 warp tile)
#pragma unroll
    for (int a = 0; a < 4; a++)
#pragma unroll
        for (int b = 0; b < 8; b++)
#pragma unroll
            for (int c = 0; c < 4; c++) acc[a][b][c] = 0.0f;

    auto compute_stage = [&](int s) {
        const char* baseA = dsm + s * STG;
        const char* baseB = baseA + TILE_B;
#pragma unroll
        for (int kk = 0; kk < 2; ++kk) {         // two k16 slabs; 32B each (interleaved)
            uint32_t af[4][4], bf[8][2];
#pragma unroll
            for (int mi = 0; mi < 4; mi++) {
                int rm = wm * 64 + mi * 16;
                uint2 lo = *(const uint2*)(baseA + (rm + g) * ROW_B + kk * 32 + tg * 8);
                uint2 hi = *(const uint2*)(baseA + (rm + g + 8) * ROW_B + kk * 32 + tg * 8);
                af[mi][0] = lo.x; af[mi][2] = lo.y;   // (a0,a2): row g, k-lo/k-hi pair
                af[mi][1] = hi.x; af[mi][3] = hi.y;   // (a1,a3): row g+8
            }
#pragma unroll
            for (int ni = 0; ni < 8; ni++) {
                int cn = wn * 64 + ni * 8 + g;
                uint2 bv = *(const uint2*)(baseB + cn * ROW_B + kk * 32 + tg * 8);
                bf[ni][0] = bv.x; bf[ni][1] = bv.y;   // (b0,b1): n-row cn, k-lo/k-hi
            }
#pragma unroll
            for (int mi = 0; mi < 4; mi++)
#pragma unroll
                for (int ni = 0; ni < 8; ni++)
                    mma16816(acc[mi][ni], af[mi], bf[ni]);
        }
    };

    // prologue: stages 0..S-2
#pragma unroll
    for (int s = 0; s < STAGES - 1; ++s) {
        load_stage(s, s);
        asm volatile("cp.async.commit_group;\n" ::: "memory");
    }
    for (int kt = 0; kt < KT; ++kt) {
        asm volatile("cp.async.wait_group %0;\n" :: "n"(STAGES - 2) : "memory");
        __syncthreads();
        if (kt + STAGES - 1 < KT) load_stage(kt + STAGES - 1, (kt + STAGES - 1) % STAGES);
        asm volatile("cp.async.commit_group;\n" ::: "memory");
        compute_stage(kt % STAGES);
    }
    asm volatile("cp.async.wait_group 0;\n" ::: "memory");

    // ---------------- epilogue ----------------
    const float* bp = bias + (size_t)e * NDIM;
#pragma unroll
    for (int mi = 0; mi < 4; mi++) {
#pragma unroll
        for (int ni = 0; ni < 8; ni++) {
            int rbase = m0 + wm * 64 + mi * 16 + g;
            int col = n0 + wn * 64 + ni * 8 + 2 * tg;           // logical column (for bias)
            float bv0 = bp[col];
            float bv1 = bp[col + 1];
            // physical (interleaved) column for H stores:
            int scol = (n0 + wn * 64 + (ni >> 1) * 16) + tg * 4 + (ni & 1) * 2;
#pragma unroll
            for (int half = 0; half < 2; half++) {
                int r = rbase + half * 8;
                if (r < cnt) {
                    float v0 = acc[mi][ni][half * 2 + 0] + bv0;
                    float v1 = acc[mi][ni][half * 2 + 1] + bv1;
                    if (PHASE1) {
                        __half2 hv = __floats2half2_rn(gelu_exact(v0), gelu_exact(v1));
                        *(__half2*)(g_H + ((size_t)e * T_TOK + r) * NDIM + scol) = hv;
                    } else {
                        int a = g_asg[e * T_TOK + r];
                        *(float2*)(g_Y + (size_t)a * NDIM + col) = make_float2(v0, v1);
                    }
                }
            }
        }
    }
}

// ---------------- kernel 6: combine Y with gates -> out ----------------
__global__ void combine_kernel(float4* __restrict__ out) {
    int i = blockIdx.x * blockDim.x + threadIdx.x;
    if (i >= T_TOK * D_DIM / 4) return;
    int t = i >> 8;
    int c = i & 255;
    float g0 = g_gates[2 * t], g1 = g_gates[2 * t + 1];
    const float4* Y = (const float4*)g_Y;
    float4 y0 = Y[((size_t)2 * t) * 256 + c];
    float4 y1 = Y[((size_t)2 * t + 1) * 256 + c];
    out[i] = make_float4(g0 * y0.x + g1 * y1.x, g0 * y0.y + g1 * y1.y,
                         g0 * y0.z + g1 * y1.z, g0 * y0.w + g1 * y1.w);
}

// ---------------- launch: side-stream overlap (R14 pattern, GEMM1 at slot 3) ------------
extern "C" void kernel_launch(void* const* d_in, const int* in_sizes, int n_in,
                              void* d_out, int out_size) {
    const float* x  = (const float*)d_in[0];
    const float* Wg = (const float*)d_in[1];
    const float* bg = (const float*)d_in[2];
    const float* W1 = (const float*)d_in[3];
    const float* b1 = (const float*)d_in[4];
    const float* W2 = (const float*)d_in[5];
    const float* b2 = (const float*)d_in[6];
    float* out = (float*)d_out;

    constexpr int SMEM_BYTES = 3 * 24576;   // 73728/CTA; x3 CTAs = 221.2KB < 228KB

    cudaFuncSetAttribute(moe_hgemm<D_DIM, F_DIM, true>,
                         cudaFuncAttributeMaxDynamicSharedMemorySize, SMEM_BYTES);
    cudaFuncSetAttribute(moe_hgemm<F_DIM, D_DIM, false>,
                         cudaFuncAttributeMaxDynamicSharedMemorySize, SMEM_BYTES);

    cudaStream_t s1;
    cudaStreamCreateWithFlags(&s1, cudaStreamNonBlocking);
    cudaEvent_t evFork, evT0, evT1;
    cudaEventCreateWithFlags(&evFork, cudaEventDisableTiming);
    cudaEventCreateWithFlags(&evT0,   cudaEventDisableTiming);
    cudaEventCreateWithFlags(&evT1,   cudaEventDisableTiming);

    cudaEventRecord(evFork, 0);
    cudaStreamWaitEvent(s1, evFork, 0);

    init_kernel<<<1, 32>>>();                                                      // slot 0 (s0)
    transpose_cvt_kernel<0><<<dim3(F_DIM / 32, D_DIM / 32, E_NUM), dim3(32, 8),
                              0, s1>>>(W1, D_DIM, F_DIM);                          // slot 1 (s1)
    cudaEventRecord(evT0, s1);
    gating_kernel<<<T_TOK / 8, 256>>>(x, Wg, bg);                                  // slot 2 (s0)
    cudaStreamWaitEvent(0, evT0, 0);                                               // t0 -> GEMM1
    moe_hgemm<D_DIM, F_DIM, true><<<dim3(F_DIM / 128, T_TOK / 128, E_NUM),
                                    128, SMEM_BYTES>>>(b1);                        // slot 3 (s0)
    transpose_cvt_kernel<1><<<dim3(D_DIM / 32, F_DIM / 32, E_NUM), dim3(32, 8),
                              0, s1>>>(W2, F_DIM, D_DIM);                          // slot 4 (s1) — overlaps GEMM1
    cudaEventRecord(evT1, s1);
    cudaStreamWaitEvent(0, evT1, 0);                                               // t1 -> GEMM2
    moe_hgemm<F_DIM, D_DIM, false><<<dim3(D_DIM / 128, T_TOK / 128, E_NUM),
                                     128, SMEM_BYTES>>>(b2);                       // slot 5 (s0)
    combine_kernel<<<(T_TOK * D_DIM / 4 + 255) / 256, 256>>>((float4*)out);        // slot 6 (s0)
}

// round 16
// speedup vs baseline: 1.0874x; 1.0874x over previous
#include <cuda_runtime.h>
#include <cuda_fp16.h>
#include <cstdint>
#include <math.h>

// Problem constants (B=4, S=2048 -> T=8192)
constexpr int T_TOK = 8192;
constexpr int D_DIM = 1024;
constexpr int F_DIM = 4096;
constexpr int E_NUM = 8;

// ---------------- device scratch (static globals; no allocation) ----------------
// All fp16 GEMM operand buffers use a k-interleaved layout: within each group of
// 16 halfs along k, logical index k sits at perm16(k). This makes each MMA
// fragment pair ((a0,a2) / (b0,b1)) one aligned 8-byte word -> LDS.64.
__device__ __half g_xh [(size_t)T_TOK * D_DIM];           //  16 MB  fp16 x (k-interleaved)
__device__ __half g_W1t[(size_t)E_NUM * F_DIM * D_DIM];   //  67 MB  W1^T [E][F][D] k-interleaved
__device__ __half g_W2t[(size_t)E_NUM * D_DIM * F_DIM];   //  67 MB  W2^T [E][D][F] k-interleaved
__device__ __half g_H  [(size_t)E_NUM * T_TOK * F_DIM];   // 537 MB  GELU hidden fp16, k-interleaved
__device__ float  g_gates[T_TOK * 2];
__device__ int    g_asg[E_NUM * T_TOK];                   // expert-local row -> token*2+slot
__device__ int    g_cnt[E_NUM];

// ---------------- helpers ----------------
// perm16: logical k (0..15) -> physical slot. Groups (2t,2t+1,2t+8,2t+9) contiguous.
__device__ __forceinline__ int perm16(int k) {
    return ((k >> 1) & 3) * 4 + ((k >> 3) & 1) * 2 + (k & 1);
}
__device__ __forceinline__ float gelu_exact(float v) {
    return 0.5f * v * (1.0f + erff(v * 0.7071067811865476f));
}
__device__ __forceinline__ uint32_t smem_u32(const void* p) {
    return (uint32_t)__cvta_generic_to_shared(p);
}
__device__ __forceinline__ void cp_async16(uint32_t dst, const void* src) {
    asm volatile("cp.async.cg.shared.global [%0], [%1], 16;\n"
                 :: "r"(dst), "l"(src) : "memory");
}
__device__ __forceinline__ void mma16816(float* c, const uint32_t* a, const uint32_t* b) {
    asm volatile(
        "mma.sync.aligned.m16n8k16.row.col.f32.f16.f16.f32 "
        "{%0,%1,%2,%3}, {%4,%5,%6,%7}, {%8,%9}, {%0,%1,%2,%3};\n"
        : "+f"(c[0]), "+f"(c[1]), "+f"(c[2]), "+f"(c[3])
        : "r"(a[0]), "r"(a[1]), "r"(a[2]), "r"(a[3]), "r"(b[0]), "r"(b[1]));
}

// ---------------- kernel 0: reset counters ----------------
__global__ void init_kernel() {
    if (threadIdx.x < E_NUM) g_cnt[threadIdx.x] = 0;
}

// ---------------- kernel 0b: zero the output (needed for fused atomic combine) ----------
__global__ void zero_out_kernel(float4* __restrict__ out) {
    int i = blockIdx.x * blockDim.x + threadIdx.x;
    if (i < T_TOK * D_DIM / 4) out[i] = make_float4(0.f, 0.f, 0.f, 0.f);
}

// ---------------- kernel 1: gating + fused x->fp16 convert (k-interleaved store) --------
__global__ void gating_kernel(const float* __restrict__ x,
                              const float* __restrict__ Wg,
                              const float* __restrict__ bg) {
    int t = blockIdx.x * 8 + (threadIdx.x >> 5);
    int lane = threadIdx.x & 31;
    float acc[E_NUM];
#pragma unroll
    for (int e = 0; e < E_NUM; e++) acc[e] = 0.0f;
    const float* xr = x + (size_t)t * D_DIM;
    __half* xo = g_xh + (size_t)t * D_DIM;
    for (int d = lane; d < D_DIM; d += 32) {
        float xv = xr[d];
        xo[(d & ~15) | perm16(d & 15)] = __float2half_rn(xv);
        const float* w = Wg + (size_t)d * E_NUM;
#pragma unroll
        for (int e = 0; e < E_NUM; e++) acc[e] += xv * w[e];
    }
#pragma unroll
    for (int e = 0; e < E_NUM; e++) {
#pragma unroll
        for (int o = 16; o > 0; o >>= 1)
            acc[e] += __shfl_xor_sync(0xffffffffu, acc[e], o);
    }
    if (lane == 0) {
        float l[E_NUM];
#pragma unroll
        for (int e = 0; e < E_NUM; e++) l[e] = acc[e] + bg[e];
        int i0 = 0;
#pragma unroll
        for (int e = 1; e < E_NUM; e++) if (l[e] > l[i0]) i0 = e;
        int i1 = (i0 == 0) ? 1 : 0;
#pragma unroll
        for (int e = 0; e < E_NUM; e++) if (e != i0 && l[e] > l[i1]) i1 = e;

        float dd = expf(l[i1] - l[i0]);
        float inv = 1.0f / (1.0f + dd);
        g_gates[2 * t]     = inv;
        g_gates[2 * t + 1] = dd * inv;
        int p0 = atomicAdd(&g_cnt[i0], 1);
        g_asg[i0 * T_TOK + p0] = 2 * t;
        int p1 = atomicAdd(&g_cnt[i1], 1);
        g_asg[i1 * T_TOK + p1] = 2 * t + 1;
    }
}

// ---------------- kernel 3: transpose + fp16 (k-interleaved store) ----------------
// dst symbol resolved in device code (GB300 ATS shadow-symbol pitfall).
template <int WHICH>   // 0 -> g_W1t, 1 -> g_W2t
__global__ void transpose_cvt_kernel(const float* __restrict__ in, int R, int C) {
    __shared__ float tile[32][33];
    __half* out = (WHICH == 0) ? g_W1t : g_W2t;
    int e = blockIdx.z;
    const float* src = in + (size_t)e * R * C;
    __half* dst = out + (size_t)e * R * C;
    int c0 = blockIdx.x * 32, r0 = blockIdx.y * 32;
    int tx = threadIdx.x, ty = threadIdx.y;
#pragma unroll
    for (int i = ty; i < 32; i += 8)
        tile[i][tx] = src[(size_t)(r0 + i) * C + c0 + tx];
    __syncthreads();
    int kp = (r0 + (tx & ~15)) | perm16(tx & 15);   // k index with intra-16 interleave
#pragma unroll
    for (int i = ty; i < 32; i += 8)
        dst[(size_t)(c0 + i) * R + kp] = __float2half_rn(tile[tx][i]);
}

// ---------------- kernels 4/5: grouped GEMM — R12/R14 core verbatim (mainloop FROZEN) ----
// LDS.64 fragments via k-interleaved operands; 64x64 warp tiles; 3 CTAs/SM; STAGES=3.
// PHASE1: H[row, n] = fp16(GELU(gather(g_xh) @ W1t[e][n,:] + b1[e,n]))   K=1024, N=4096
// PHASE2: out[tok, n] += gate * (H[row,:] @ W2t[e][n,:] + b2[e,n])       K=4096, N=1024
//         (fused combine: deterministic — each out element gets exactly 2 fp addends)
template <int KDIM, int NDIM, bool PHASE1>
__global__ void __launch_bounds__(128, 3)
moe_hgemm(const float* __restrict__ bias, float* __restrict__ outp) {
    constexpr int BM = 128, BN = 128, BK = 32, STAGES = 3;
    constexpr int ROW_B = 96;                    // padded row stride in bytes (24 words)
    constexpr int TILE_B = BM * ROW_B;           // 12288 bytes per operand tile
    constexpr int STG = 2 * TILE_B;              // 24576 bytes per stage
    constexpr int KT = KDIM / BK;

    extern __shared__ __align__(16) char dsm[];
    __shared__ int s_tok[BM];

    const int e = blockIdx.z;
    const int cnt = g_cnt[e];
    const int m0 = blockIdx.y * BM;
    if (m0 >= cnt) return;
    const int n0 = blockIdx.x * BN;
    const int tid = threadIdx.x;

    const __half* Ab = PHASE1 ? g_xh : (g_H + ((size_t)e * T_TOK + m0) * KDIM);
    const __half* Bb = (PHASE1 ? g_W1t : g_W2t) + ((size_t)e * NDIM + n0) * KDIM;

    if (PHASE1) {
        int m = m0 + tid;
        s_tok[tid] = (m < cnt) ? (g_asg[e * T_TOK + m] >> 1) : 0;  // pad rows read token 0
        __syncthreads();
    }

    const uint32_t sbase = smem_u32(dsm);

    auto load_stage = [&](int kt, int s) {
        uint32_t stA = sbase + s * STG;
        uint32_t stB = stA + TILE_B;
#pragma unroll
        for (int i = 0; i < 4; ++i) {            // 512 16B-chunks per operand, 128 threads
            int idx = tid + i * 128;
            int r = idx >> 2, c = idx & 3;       // row 0..127, chunk 0..3 (16B = 8 halfs)
            const __half* asrc;
            if (PHASE1) {
                asrc = Ab + (size_t)s_tok[r] * KDIM + kt * BK + c * 8;
            } else {
                int m = m0 + r;
                asrc = Ab + (size_t)(m < cnt ? r : 0) * KDIM + kt * BK + c * 8;
            }
            cp_async16(stA + r * ROW_B + c * 16, asrc);
            cp_async16(stB + r * ROW_B + c * 16,
                       Bb + (size_t)r * KDIM + kt * BK + c * 8);
        }
    };

    const int lane = tid & 31;
    const int warp = tid >> 5;
    const int wm = warp & 1;        // 2 warps over M (64 rows each)
    const int wn = warp >> 1;       // 2 warps over N (64 cols each)
    const int g = lane >> 2, tg = lane & 3;

    float acc[4][8][4];             // mi x ni x frag  (64x64 warp tile)
#pragma unroll
    for (int a = 0; a < 4; a++)
#pragma unroll
        for (int b = 0; b < 8; b++)
#pragma unroll
            for (int c = 0; c < 4; c++) acc[a][b][c] = 0.0f;

    auto compute_stage = [&](int s) {
        const char* baseA = dsm + s * STG;
        const char* baseB = baseA + TILE_B;
#pragma unroll
        for (int kk = 0; kk < 2; ++kk) {         // two k16 slabs; 32B each (interleaved)
            uint32_t af[4][4], bf[8][2];
#pragma unroll
            for (int mi = 0; mi < 4; mi++) {
                int rm = wm * 64 + mi * 16;
                uint2 lo = *(const uint2*)(baseA + (rm + g) * ROW_B + kk * 32 + tg * 8);
                uint2 hi = *(const uint2*)(baseA + (rm + g + 8) * ROW_B + kk * 32 + tg * 8);
                af[mi][0] = lo.x; af[mi][2] = lo.y;   // (a0,a2): row g, k-lo/k-hi pair
                af[mi][1] = hi.x; af[mi][3] = hi.y;   // (a1,a3): row g+8
            }
#pragma unroll
            for (int ni = 0; ni < 8; ni++) {
                int cn = wn * 64 + ni * 8 + g;
                uint2 bv = *(const uint2*)(baseB + cn * ROW_B + kk * 32 + tg * 8);
                bf[ni][0] = bv.x; bf[ni][1] = bv.y;   // (b0,b1): n-row cn, k-lo/k-hi
            }
#pragma unroll
            for (int mi = 0; mi < 4; mi++)
#pragma unroll
                for (int ni = 0; ni < 8; ni++)
                    mma16816(acc[mi][ni], af[mi], bf[ni]);
        }
    };

    // prologue: stages 0..S-2
#pragma unroll
    for (int s = 0; s < STAGES - 1; ++s) {
        load_stage(s, s);
        asm volatile("cp.async.commit_group;\n" ::: "memory");
    }
    for (int kt = 0; kt < KT; ++kt) {
        asm volatile("cp.async.wait_group %0;\n" :: "n"(STAGES - 2) : "memory");
        __syncthreads();
        if (kt + STAGES - 1 < KT) load_stage(kt + STAGES - 1, (kt + STAGES - 1) % STAGES);
        asm volatile("cp.async.commit_group;\n" ::: "memory");
        compute_stage(kt % STAGES);
    }
    asm volatile("cp.async.wait_group 0;\n" ::: "memory");

    // ---------------- epilogue ----------------
    const float* bp = bias + (size_t)e * NDIM;
#pragma unroll
    for (int mi = 0; mi < 4; mi++) {
        // per-row data (hoisted): assignment + gate for the two row-halves
        int rows[2];
        int asgv[2];
        float gatev[2];
#pragma unroll
        for (int half = 0; half < 2; half++) {
            int r = m0 + wm * 64 + mi * 16 + g + half * 8;
            rows[half] = r;
            if (!PHASE1 && r < cnt) {
                int a = g_asg[e * T_TOK + r];
                asgv[half] = a;
                gatev[half] = g_gates[a];
            }
        }
#pragma unroll
        for (int ni = 0; ni < 8; ni++) {
            int col = n0 + wn * 64 + ni * 8 + 2 * tg;           // logical column (for bias)
            float bv0 = bp[col];
            float bv1 = bp[col + 1];
            // physical (interleaved) column for H stores:
            int scol = (n0 + wn * 64 + (ni >> 1) * 16) + tg * 4 + (ni & 1) * 2;
#pragma unroll
            for (int half = 0; half < 2; half++) {
                int r = rows[half];
                if (r < cnt) {
                    float v0 = acc[mi][ni][half * 2 + 0] + bv0;
                    float v1 = acc[mi][ni][half * 2 + 1] + bv1;
                    if (PHASE1) {
                        __half2 hv = __floats2half2_rn(gelu_exact(v0), gelu_exact(v1));
                        *(__half2*)(g_H + ((size_t)e * T_TOK + r) * NDIM + scol) = hv;
                    } else {
                        float gate = gatev[half];
                        float* orow = outp + (size_t)(asgv[half] >> 1) * NDIM + col;
                        atomicAdd(orow,     gate * v0);
                        atomicAdd(orow + 1, gate * v1);
                    }
                }
            }
        }
    }
}

// ---------------- launch: side-stream overlap (GEMM1 at slot 3); fused combine ----------
// Dependencies: t0 -> GEMM1; {t1, zero_out} -> GEMM2; {init,gating} -> GEMM1.
// zero_out + transpose1 run on side stream s1 hidden under GEMM1; joined via evT1.
extern "C" void kernel_launch(void* const* d_in, const int* in_sizes, int n_in,
                              void* d_out, int out_size) {
    const float* x  = (const float*)d_in[0];
    const float* Wg = (const float*)d_in[1];
    const float* bg = (const float*)d_in[2];
    const float* W1 = (const float*)d_in[3];
    const float* b1 = (const float*)d_in[4];
    const float* W2 = (const float*)d_in[5];
    const float* b2 = (const float*)d_in[6];
    float* out = (float*)d_out;

    constexpr int SMEM_BYTES = 3 * 24576;   // 73728/CTA; x3 CTAs = 221.2KB < 228KB

    cudaFuncSetAttribute(moe_hgemm<D_DIM, F_DIM, true>,
                         cudaFuncAttributeMaxDynamicSharedMemorySize, SMEM_BYTES);
    cudaFuncSetAttribute(moe_hgemm<F_DIM, D_DIM, false>,
                         cudaFuncAttributeMaxDynamicSharedMemorySize, SMEM_BYTES);

    cudaStream_t s1;
    cudaStreamCreateWithFlags(&s1, cudaStreamNonBlocking);
    cudaEvent_t evFork, evT0, evT1;
    cudaEventCreateWithFlags(&evFork, cudaEventDisableTiming);
    cudaEventCreateWithFlags(&evT0,   cudaEventDisableTiming);
    cudaEventCreateWithFlags(&evT1,   cudaEventDisableTiming);

    cudaEventRecord(evFork, 0);
    cudaStreamWaitEvent(s1, evFork, 0);

    init_kernel<<<1, 32>>>();                                                      // slot 0 (s0)
    transpose_cvt_kernel<0><<<dim3(F_DIM / 32, D_DIM / 32, E_NUM), dim3(32, 8),
                              0, s1>>>(W1, D_DIM, F_DIM);                          // slot 1 (s1)
    cudaEventRecord(evT0, s1);
    gating_kernel<<<T_TOK / 8, 256>>>(x, Wg, bg);                                  // slot 2 (s0)
    cudaStreamWaitEvent(0, evT0, 0);                                               // t0 -> GEMM1
    moe_hgemm<D_DIM, F_DIM, true><<<dim3(F_DIM / 128, T_TOK / 128, E_NUM),
                                    128, SMEM_BYTES>>>(b1, nullptr);               // slot 3 (s0)
    zero_out_kernel<<<(T_TOK * D_DIM / 4 + 255) / 256, 256, 0, s1>>>((float4*)out); // slot 4 (s1)
    transpose_cvt_kernel<1><<<dim3(D_DIM / 32, F_DIM / 32, E_NUM), dim3(32, 8),
                              0, s1>>>(W2, F_DIM, D_DIM);                          // slot 5 (s1) — overlaps GEMM1
    cudaEventRecord(evT1, s1);
    cudaStreamWaitEvent(0, evT1, 0);                                               // {zero,t1} -> GEMM2
    moe_hgemm<F_DIM, D_DIM, false><<<dim3(D_DIM / 128, T_TOK / 128, E_NUM),
                                     128, SMEM_BYTES>>>(b2, out);                  // slot 6 (s0)
}